// round 16
// baseline (speedup 1.0000x reference)
#include <cuda_runtime.h>
#include <math.h>

// Problem: tensor [8192, 256] fp32.
// out = (adj @ X) where adj = rownorm(cosine_sim(X)).
// Factored: M = X_hat^T X (256x256, SYMMETRIC), s = sum_j x_hat_j (256),
//           out[i] = (x_i @ M) / (x_i . s)   (inv-norm cancels).
// Denominator via compensated fp32 Dot2. Two kernels w/ intra-kernel gates.
// k_out: 8x4 thread tiles (128x64 block) -> FFMA-bound instead of smem+FFMA
// co-bound. GCHUNKS=32 halves Mpart traffic.

#define NROWS 8192
#define DDIM  256
#define GCHUNKS 32
#define SCHUNKS 256
#define NTILES  10

#define NB_NORM 256
#define NB_GRAM 320
#define NB_RED  160
#define NB_RINV 128
#define NB_OUT  256

__device__ float  g_invn[NROWS];
__device__ float2 g_spart[SCHUNKS][DDIM];
__device__ float2 g_s2[DDIM];
__device__ float  g_rinv[NROWS];
__device__ float  g_Mpart[GCHUNKS][NTILES][64 * 64];
__device__ float  g_M[DDIM * DDIM];
__device__ int    g_c[3];    // counters: 0=norm, 1=reduce, 2=rinv

__device__ const int c_TI[NTILES] = {0,0,0,0,1,1,1,2,2,3};
__device__ const int c_TJ[NTILES] = {0,1,2,3,1,2,3,2,3,3};

// ---- error-free fp32 transforms ------------------------------------------
__device__ __forceinline__ void twoSum(float a, float b, float& s, float& e) {
    s = a + b;
    float bb = s - a;
    e = (a - (s - bb)) + (b - bb);
}
__device__ __forceinline__ void twoProd(float a, float b, float& p, float& e) {
    p = a * b;
    e = fmaf(a, b, -p);
}

// ---- phase gates -----------------------------------------------------------
__device__ __forceinline__ void wait_cnt(int idx, int target) {
    if (threadIdx.x == 0) {
        while (*(volatile int*)&g_c[idx] < target) __nanosleep(128);
    }
    __syncthreads();
}
__device__ __forceinline__ void release_cnt(int idx) {
    __threadfence();
    __syncthreads();
    if (threadIdx.x == 0) atomicAdd(&g_c[idx], 1);
}

// ---------------------------------------------------------------------------
// K1: norm (blocks [0,256)) + gram (blocks [256,576), gated on c0).
// gram: 32 k-chunks x 256 rows, 10 upper-triangle 64x64 tiles, 4x4/thread,
// double-buffered panels of 8.
// ---------------------------------------------------------------------------
__global__ void __launch_bounds__(256) k_norm_gram(const float* __restrict__ X) {
    const int bid  = blockIdx.x;
    const int tid  = threadIdx.x;
    const int wid  = tid >> 5;
    const int lane = tid & 31;

    if (bid < NB_NORM) {
        // ---- norm phase ----
        __shared__ float invn_sh[32];
        const int row0 = bid * 32;

        for (int r = wid; r < 32; r += 8) {
            const float4* p = reinterpret_cast<const float4*>(X + (size_t)(row0 + r) * DDIM);
            float ss = 0.f;
            #pragma unroll
            for (int q = 0; q < 2; q++) {
                float4 v = p[lane + q * 32];
                ss += v.x * v.x + v.y * v.y + v.z * v.z + v.w * v.w;
            }
            #pragma unroll
            for (int o = 16; o > 0; o >>= 1) ss += __shfl_xor_sync(0xffffffffu, ss, o);
            if (lane == 0) {
                float inv = 1.0f / fmaxf(sqrtf(ss), 1e-8f);
                invn_sh[r]       = inv;
                g_invn[row0 + r] = inv;
            }
        }
        __syncthreads();

        float s = 0.f, c = 0.f;
        #pragma unroll
        for (int r = 0; r < 32; r++) {
            float p, e, t1;
            twoProd(invn_sh[r], X[(size_t)(row0 + r) * DDIM + tid], p, e);
            twoSum(s, p, s, t1);
            c += t1 + e;
        }
        g_spart[bid][tid] = make_float2(s, c);
        release_cnt(0);
        return;
    }

    // ---- gram phase ----
    wait_cnt(0, NB_NORM);

    __shared__ float SA[2][8][64];
    __shared__ float SB[2][8][64];

    const int id2 = bid - NB_NORM;
    const int c_  = id2 & 31;          // k-chunk (256 rows)
    const int t   = id2 >> 5;          // tile 0..9
    const int ti = c_TI[t];
    const int tj = c_TJ[t];
    const int tx = tid & 15;
    const int ty = (tid >> 4) & 15;
    const int side = tid >> 7;
    const int li   = (tid >> 4) & 7;
    const int lf   = tid & 15;
    const int rowbase = c_ * 256;
    const int colbase = (side == 0 ? ti : tj) * 64;

    float T[4][4];
    #pragma unroll
    for (int i = 0; i < 4; i++)
        #pragma unroll
        for (int j = 0; j < 4; j++) T[i][j] = 0.f;

    {
        const int gr = rowbase + li;
        float4 v = *reinterpret_cast<const float4*>(X + (size_t)gr * DDIM + colbase + lf * 4);
        if (side == 0) {
            const float sc = g_invn[gr];
            *reinterpret_cast<float4*>(&SA[0][li][lf * 4]) =
                make_float4(v.x * sc, v.y * sc, v.z * sc, v.w * sc);
        } else {
            *reinterpret_cast<float4*>(&SB[0][li][lf * 4]) = v;
        }
    }
    __syncthreads();

    for (int s = 0; s < 32; s++) {
        const int p = s & 1;
        float4 vn;
        float scn = 1.f;
        if (s < 31) {
            const int gr = rowbase + (s + 1) * 8 + li;
            vn = *reinterpret_cast<const float4*>(X + (size_t)gr * DDIM + colbase + lf * 4);
            if (side == 0) scn = g_invn[gr];
        }
        #pragma unroll
        for (int r = 0; r < 8; r++) {
            float4 a = *reinterpret_cast<const float4*>(&SA[p][r][ty * 4]);
            float4 b = *reinterpret_cast<const float4*>(&SB[p][r][tx * 4]);
            const float aa[4] = {a.x, a.y, a.z, a.w};
            const float bb[4] = {b.x, b.y, b.z, b.w};
            #pragma unroll
            for (int i = 0; i < 4; i++)
                #pragma unroll
                for (int j = 0; j < 4; j++) T[i][j] += aa[i] * bb[j];
        }
        if (s < 31) {
            if (side == 0)
                *reinterpret_cast<float4*>(&SA[p ^ 1][li][lf * 4]) =
                    make_float4(vn.x * scn, vn.y * scn, vn.z * scn, vn.w * scn);
            else
                *reinterpret_cast<float4*>(&SB[p ^ 1][li][lf * 4]) = vn;
        }
        __syncthreads();
    }

    float* out = &g_Mpart[c_][t][0];
    #pragma unroll
    for (int i = 0; i < 4; i++)
        *reinterpret_cast<float4*>(&out[(ty * 4 + i) * 64 + tx * 4]) =
            make_float4(T[i][0], T[i][1], T[i][2], T[i][3]);
}

// ---------------------------------------------------------------------------
// K2: reduce (blocks [0,160)) + rinv ([160,288), gated on c1)
//     + out-GEMM ([288,544), 8x4 tiles, gated on c1 / c2).
// ---------------------------------------------------------------------------
__global__ void __launch_bounds__(256) k_red_out(const float* __restrict__ X,
                                                 float* __restrict__ OUT) {
    const int bid  = blockIdx.x;
    const int tid  = threadIdx.x;
    const int wid  = tid >> 5;
    const int lane = tid & 31;

    if (bid < NB_RED) {
        // ---- reduce phase ----
        const int idx = bid * 256 + tid;
        const int t = idx >> 12;
        const int e = idx & 4095;
        float s = 0.f, comp = 0.f;
        #pragma unroll
        for (int c = 0; c < GCHUNKS; c++) {
            float t1;
            twoSum(s, g_Mpart[c][t][e], s, t1);
            comp += t1;
        }
        const float v = s + comp;
        const int k = c_TI[t] * 64 + (e >> 6);
        const int l = c_TJ[t] * 64 + (e & 63);
        if (k < l) {
            g_M[k * DDIM + l] = v;
            g_M[l * DDIM + k] = v;
        } else if (k == l) {
            g_M[k * DDIM + l] = v;
        }

        if (bid == 0) {
            float sa = 0.f, ca = 0.f;
            #pragma unroll 8
            for (int b = 0; b < SCHUNKS; b++) {
                float2 p = g_spart[b][tid];
                float t1;
                twoSum(sa, p.x, sa, t1);
                ca += t1 + p.y;
            }
            g_s2[tid] = make_float2(sa, ca);
        }
        release_cnt(1);
        return;
    }

    if (bid < NB_RED + NB_RINV) {
        // ---- rinv phase ----
        wait_cnt(1, NB_RED);
        __threadfence();

        __shared__ float2 s_sh[DDIM];
        s_sh[tid] = g_s2[tid];
        __syncthreads();

        const int id2 = bid - NB_RED;
        #pragma unroll
        for (int rr = 0; rr < 8; rr++) {
            const int row = id2 * 64 + wid * 8 + rr;
            const float4* xp4 = reinterpret_cast<const float4*>(X + (size_t)row * DDIM);
            float s = 0.f, c = 0.f;
            #pragma unroll
            for (int q = 0; q < 2; q++) {
                const int f = lane + q * 32;
                const float4 xv = xp4[f];
                const float xs[4] = {xv.x, xv.y, xv.z, xv.w};
                #pragma unroll
                for (int m = 0; m < 4; m++) {
                    const float2 sv = s_sh[f * 4 + m];
                    float p, e, t1;
                    twoProd(xs[m], sv.x, p, e);
                    e = fmaf(xs[m], sv.y, e);
                    twoSum(s, p, s, t1);
                    c += t1 + e;
                }
            }
            #pragma unroll
            for (int o = 16; o > 0; o >>= 1) {
                float s2 = __shfl_xor_sync(0xffffffffu, s, o);
                float c2 = __shfl_xor_sync(0xffffffffu, c, o);
                float t1;
                twoSum(s, s2, s, t1);
                c += c2 + t1;
            }
            if (lane == 0) {
                double den = (double)s + (double)c;
                g_rinv[row] = (float)(1.0 / den);
            }
        }
        release_cnt(2);
        return;
    }

    // ---- out-GEMM phase: 128(M)x64(N) block tile, 8x4 per thread ----
    wait_cnt(1, NB_RED);
    __threadfence();

    __shared__ float SA[2][8][132];   // [k][row], stride 132 (conflict-free)
    __shared__ float SB[2][8][64];

    const int id2  = bid - (NB_RED + NB_RINV);
    const int row0 = (id2 >> 2) * 128;
    const int c0   = (id2 & 3) * 64;
    const int tx   = tid & 15;        // 16 cols of 4
    const int ty   = tid >> 4;        // 16 rows of 8

    const int ar = tid >> 1;          // SA staging: row 0..127
    const int ah = tid & 1;           // SA staging: k-half
    const int bi = (tid >> 4) & 7;    // SB staging (tid<128): stage row
    const int bf = tid & 15;          // SB staging: float4 slot

    float T[8][4];
    #pragma unroll
    for (int i = 0; i < 8; i++)
        #pragma unroll
        for (int j = 0; j < 4; j++) T[i][j] = 0.f;

    // prologue: stage panel 0
    {
        float4 v = *reinterpret_cast<const float4*>(X + (size_t)(row0 + ar) * DDIM + ah * 4);
        SA[0][ah * 4 + 0][ar] = v.x;
        SA[0][ah * 4 + 1][ar] = v.y;
        SA[0][ah * 4 + 2][ar] = v.z;
        SA[0][ah * 4 + 3][ar] = v.w;
        if (tid < 128) {
            *reinterpret_cast<float4*>(&SB[0][bi][bf * 4]) =
                *reinterpret_cast<const float4*>(&g_M[bi * DDIM + c0 + bf * 4]);
        }
    }
    __syncthreads();

    for (int s = 0; s < 32; s++) {
        const int p = s & 1;
        float4 va, vb;
        if (s < 31) {
            const int k1 = (s + 1) * 8;
            va = *reinterpret_cast<const float4*>(X + (size_t)(row0 + ar) * DDIM + k1 + ah * 4);
            if (tid < 128)
                vb = *reinterpret_cast<const float4*>(&g_M[(k1 + bi) * DDIM + c0 + bf * 4]);
        }
        #pragma unroll
        for (int r = 0; r < 8; r++) {
            float4 a0 = *reinterpret_cast<const float4*>(&SA[p][r][ty * 8]);
            float4 a1 = *reinterpret_cast<const float4*>(&SA[p][r][ty * 8 + 4]);
            float4 b  = *reinterpret_cast<const float4*>(&SB[p][r][tx * 4]);
            const float aa[8] = {a0.x, a0.y, a0.z, a0.w, a1.x, a1.y, a1.z, a1.w};
            const float bb[4] = {b.x, b.y, b.z, b.w};
            #pragma unroll
            for (int i = 0; i < 8; i++)
                #pragma unroll
                for (int j = 0; j < 4; j++) T[i][j] += aa[i] * bb[j];
        }
        if (s < 31) {
            SA[p ^ 1][ah * 4 + 0][ar] = va.x;
            SA[p ^ 1][ah * 4 + 1][ar] = va.y;
            SA[p ^ 1][ah * 4 + 2][ar] = va.z;
            SA[p ^ 1][ah * 4 + 3][ar] = va.w;
            if (tid < 128)
                *reinterpret_cast<float4*>(&SB[p ^ 1][bi][bf * 4]) = vb;
        }
        __syncthreads();
    }

    // wait for rinv release (normally already satisfied)
    if (tid == 0) {
        while (*(volatile int*)&g_c[2] < NB_RINV) __nanosleep(64);
    }
    __syncthreads();

    #pragma unroll
    for (int i = 0; i < 8; i++) {
        const int m = row0 + ty * 8 + i;
        const float rv = __ldcg(&g_rinv[m]);
        *reinterpret_cast<float4*>(&OUT[(size_t)m * DDIM + c0 + tx * 4]) =
            make_float4(T[i][0] * rv, T[i][1] * rv, T[i][2] * rv, T[i][3] * rv);
    }
}

extern "C" void kernel_launch(void* const* d_in, const int* in_sizes, int n_in,
                              void* d_out, int out_size) {
    (void)in_sizes; (void)n_in; (void)out_size;
    const float* X = (const float*)d_in[0];
    float* OUT     = (float*)d_out;

    void* cp = 0;
    cudaGetSymbolAddress(&cp, g_c);
    cudaMemsetAsync(cp, 0, 3 * sizeof(int));

    k_norm_gram<<<NB_NORM + NB_GRAM, 256>>>(X);
    k_red_out<<<NB_RED + NB_RINV + NB_OUT, 256>>>(X, OUT);
}

// round 17
// speedup vs baseline: 1.1715x; 1.1715x over previous
#include <cuda_runtime.h>
#include <math.h>

// Problem: tensor [8192, 256] fp32.
// out = (adj @ X) where adj = rownorm(cosine_sim(X)).
// Factored: M = X_hat^T X (256x256, SYMMETRIC), s = sum_j x_hat_j (256),
//           out[i] = (x_i @ M) / (x_i . s)   (inv-norm cancels).
// Denominator via compensated fp32 Dot2. Two kernels w/ intra-kernel gates.
// gram: GCHUNKS=64 (640 blocks — 32 measured slower: single-wave 2x-work).
// out-GEMM: 128x64 block tile, 8x4/thread (FFMA-bound, not smem co-bound).

#define NROWS 8192
#define DDIM  256
#define GCHUNKS 64
#define SCHUNKS 256
#define NTILES  10

#define NB_NORM 256
#define NB_GRAM 640
#define NB_RED  160
#define NB_RINV 128
#define NB_OUT  256

__device__ float  g_invn[NROWS];
__device__ float2 g_spart[SCHUNKS][DDIM];
__device__ float2 g_s2[DDIM];
__device__ float  g_rinv[NROWS];
__device__ float  g_Mpart[GCHUNKS][NTILES][64 * 64];
__device__ float  g_M[DDIM * DDIM];
__device__ int    g_c[3];    // counters: 0=norm, 1=reduce, 2=rinv

__device__ const int c_TI[NTILES] = {0,0,0,0,1,1,1,2,2,3};
__device__ const int c_TJ[NTILES] = {0,1,2,3,1,2,3,2,3,3};

// ---- error-free fp32 transforms ------------------------------------------
__device__ __forceinline__ void twoSum(float a, float b, float& s, float& e) {
    s = a + b;
    float bb = s - a;
    e = (a - (s - bb)) + (b - bb);
}
__device__ __forceinline__ void twoProd(float a, float b, float& p, float& e) {
    p = a * b;
    e = fmaf(a, b, -p);
}

// ---- phase gates -----------------------------------------------------------
__device__ __forceinline__ void wait_cnt(int idx, int target) {
    if (threadIdx.x == 0) {
        while (*(volatile int*)&g_c[idx] < target) __nanosleep(128);
    }
    __syncthreads();
}
__device__ __forceinline__ void release_cnt(int idx) {
    __threadfence();
    __syncthreads();
    if (threadIdx.x == 0) atomicAdd(&g_c[idx], 1);
}

// ---------------------------------------------------------------------------
// K1: norm (blocks [0,256)) + gram (blocks [256,896), gated on c0).
// ---------------------------------------------------------------------------
__global__ void __launch_bounds__(256) k_norm_gram(const float* __restrict__ X) {
    const int bid  = blockIdx.x;
    const int tid  = threadIdx.x;
    const int wid  = tid >> 5;
    const int lane = tid & 31;

    if (bid < NB_NORM) {
        // ---- norm phase ----
        __shared__ float invn_sh[32];
        const int row0 = bid * 32;

        for (int r = wid; r < 32; r += 8) {
            const float4* p = reinterpret_cast<const float4*>(X + (size_t)(row0 + r) * DDIM);
            float ss = 0.f;
            #pragma unroll
            for (int q = 0; q < 2; q++) {
                float4 v = p[lane + q * 32];
                ss += v.x * v.x + v.y * v.y + v.z * v.z + v.w * v.w;
            }
            #pragma unroll
            for (int o = 16; o > 0; o >>= 1) ss += __shfl_xor_sync(0xffffffffu, ss, o);
            if (lane == 0) {
                float inv = 1.0f / fmaxf(sqrtf(ss), 1e-8f);
                invn_sh[r]       = inv;
                g_invn[row0 + r] = inv;
            }
        }
        __syncthreads();

        float s = 0.f, c = 0.f;
        #pragma unroll
        for (int r = 0; r < 32; r++) {
            float p, e, t1;
            twoProd(invn_sh[r], X[(size_t)(row0 + r) * DDIM + tid], p, e);
            twoSum(s, p, s, t1);
            c += t1 + e;
        }
        g_spart[bid][tid] = make_float2(s, c);
        release_cnt(0);
        return;
    }

    // ---- gram phase ----
    wait_cnt(0, NB_NORM);

    __shared__ float SA[2][8][64];
    __shared__ float SB[2][8][64];

    const int id2 = bid - NB_NORM;
    const int c_  = id2 & 63;          // k-chunk (128 rows)
    const int t   = id2 >> 6;          // tile 0..9
    const int ti = c_TI[t];
    const int tj = c_TJ[t];
    const int tx = tid & 15;
    const int ty = (tid >> 4) & 15;
    const int side = tid >> 7;
    const int li   = (tid >> 4) & 7;
    const int lf   = tid & 15;
    const int rowbase = c_ * 128;
    const int colbase = (side == 0 ? ti : tj) * 64;

    float T[4][4];
    #pragma unroll
    for (int i = 0; i < 4; i++)
        #pragma unroll
        for (int j = 0; j < 4; j++) T[i][j] = 0.f;

    {
        const int gr = rowbase + li;
        float4 v = *reinterpret_cast<const float4*>(X + (size_t)gr * DDIM + colbase + lf * 4);
        if (side == 0) {
            const float sc = g_invn[gr];
            *reinterpret_cast<float4*>(&SA[0][li][lf * 4]) =
                make_float4(v.x * sc, v.y * sc, v.z * sc, v.w * sc);
        } else {
            *reinterpret_cast<float4*>(&SB[0][li][lf * 4]) = v;
        }
    }
    __syncthreads();

    for (int s = 0; s < 16; s++) {
        const int p = s & 1;
        float4 vn;
        float scn = 1.f;
        if (s < 15) {
            const int gr = rowbase + (s + 1) * 8 + li;
            vn = *reinterpret_cast<const float4*>(X + (size_t)gr * DDIM + colbase + lf * 4);
            if (side == 0) scn = g_invn[gr];
        }
        #pragma unroll
        for (int r = 0; r < 8; r++) {
            float4 a = *reinterpret_cast<const float4*>(&SA[p][r][ty * 4]);
            float4 b = *reinterpret_cast<const float4*>(&SB[p][r][tx * 4]);
            const float aa[4] = {a.x, a.y, a.z, a.w};
            const float bb[4] = {b.x, b.y, b.z, b.w};
            #pragma unroll
            for (int i = 0; i < 4; i++)
                #pragma unroll
                for (int j = 0; j < 4; j++) T[i][j] += aa[i] * bb[j];
        }
        if (s < 15) {
            if (side == 0)
                *reinterpret_cast<float4*>(&SA[p ^ 1][li][lf * 4]) =
                    make_float4(vn.x * scn, vn.y * scn, vn.z * scn, vn.w * scn);
            else
                *reinterpret_cast<float4*>(&SB[p ^ 1][li][lf * 4]) = vn;
        }
        __syncthreads();
    }

    float* out = &g_Mpart[c_][t][0];
    #pragma unroll
    for (int i = 0; i < 4; i++)
        *reinterpret_cast<float4*>(&out[(ty * 4 + i) * 64 + tx * 4]) =
            make_float4(T[i][0], T[i][1], T[i][2], T[i][3]);
}

// ---------------------------------------------------------------------------
// K2: reduce (blocks [0,160)) + rinv ([160,288), gated on c1)
//     + out-GEMM ([288,544), 128x64 tiles 8x4/thread, gated on c1 / c2).
// ---------------------------------------------------------------------------
__global__ void __launch_bounds__(256) k_red_out(const float* __restrict__ X,
                                                 float* __restrict__ OUT) {
    const int bid  = blockIdx.x;
    const int tid  = threadIdx.x;
    const int wid  = tid >> 5;
    const int lane = tid & 31;

    if (bid < NB_RED) {
        // ---- reduce phase ----
        const int idx = bid * 256 + tid;
        const int t = idx >> 12;
        const int e = idx & 4095;
        float s = 0.f, comp = 0.f;
        #pragma unroll
        for (int c = 0; c < GCHUNKS; c++) {
            float t1;
            twoSum(s, g_Mpart[c][t][e], s, t1);
            comp += t1;
        }
        const float v = s + comp;
        const int k = c_TI[t] * 64 + (e >> 6);
        const int l = c_TJ[t] * 64 + (e & 63);
        if (k < l) {
            g_M[k * DDIM + l] = v;
            g_M[l * DDIM + k] = v;
        } else if (k == l) {
            g_M[k * DDIM + l] = v;
        }

        if (bid == 0) {
            float sa = 0.f, ca = 0.f;
            #pragma unroll 8
            for (int b = 0; b < SCHUNKS; b++) {
                float2 p = g_spart[b][tid];
                float t1;
                twoSum(sa, p.x, sa, t1);
                ca += t1 + p.y;
            }
            g_s2[tid] = make_float2(sa, ca);
        }
        release_cnt(1);
        return;
    }

    if (bid < NB_RED + NB_RINV) {
        // ---- rinv phase ----
        wait_cnt(1, NB_RED);
        __threadfence();

        __shared__ float2 s_sh[DDIM];
        s_sh[tid] = g_s2[tid];
        __syncthreads();

        const int id2 = bid - NB_RED;
        #pragma unroll
        for (int rr = 0; rr < 8; rr++) {
            const int row = id2 * 64 + wid * 8 + rr;
            const float4* xp4 = reinterpret_cast<const float4*>(X + (size_t)row * DDIM);
            float s = 0.f, c = 0.f;
            #pragma unroll
            for (int q = 0; q < 2; q++) {
                const int f = lane + q * 32;
                const float4 xv = xp4[f];
                const float xs[4] = {xv.x, xv.y, xv.z, xv.w};
                #pragma unroll
                for (int m = 0; m < 4; m++) {
                    const float2 sv = s_sh[f * 4 + m];
                    float p, e, t1;
                    twoProd(xs[m], sv.x, p, e);
                    e = fmaf(xs[m], sv.y, e);
                    twoSum(s, p, s, t1);
                    c += t1 + e;
                }
            }
            #pragma unroll
            for (int o = 16; o > 0; o >>= 1) {
                float s2 = __shfl_xor_sync(0xffffffffu, s, o);
                float c2 = __shfl_xor_sync(0xffffffffu, c, o);
                float t1;
                twoSum(s, s2, s, t1);
                c += c2 + t1;
            }
            if (lane == 0) {
                double den = (double)s + (double)c;
                g_rinv[row] = (float)(1.0 / den);
            }
        }
        release_cnt(2);
        return;
    }

    // ---- out-GEMM phase: 128(M)x64(N) block tile, 8x4 per thread ----
    wait_cnt(1, NB_RED);
    __threadfence();

    __shared__ float SA[2][8][132];   // [k][row], stride 132 (conflict-free)
    __shared__ float SB[2][8][64];

    const int id2  = bid - (NB_RED + NB_RINV);
    const int row0 = (id2 >> 2) * 128;
    const int c0   = (id2 & 3) * 64;
    const int tx   = tid & 15;        // 16 cols of 4
    const int ty   = tid >> 4;        // 16 rows of 8

    const int ar = tid >> 1;          // SA staging: row 0..127
    const int ah = tid & 1;           // SA staging: k-half
    const int bi = (tid >> 4) & 7;    // SB staging (tid<128): stage row
    const int bf = tid & 15;          // SB staging: float4 slot

    float T[8][4];
    #pragma unroll
    for (int i = 0; i < 8; i++)
        #pragma unroll
        for (int j = 0; j < 4; j++) T[i][j] = 0.f;

    // prologue: stage panel 0
    {
        float4 v = *reinterpret_cast<const float4*>(X + (size_t)(row0 + ar) * DDIM + ah * 4);
        SA[0][ah * 4 + 0][ar] = v.x;
        SA[0][ah * 4 + 1][ar] = v.y;
        SA[0][ah * 4 + 2][ar] = v.z;
        SA[0][ah * 4 + 3][ar] = v.w;
        if (tid < 128) {
            *reinterpret_cast<float4*>(&SB[0][bi][bf * 4]) =
                *reinterpret_cast<const float4*>(&g_M[bi * DDIM + c0 + bf * 4]);
        }
    }
    __syncthreads();

    for (int s = 0; s < 32; s++) {
        const int p = s & 1;
        float4 va, vb;
        if (s < 31) {
            const int k1 = (s + 1) * 8;
            va = *reinterpret_cast<const float4*>(X + (size_t)(row0 + ar) * DDIM + k1 + ah * 4);
            if (tid < 128)
                vb = *reinterpret_cast<const float4*>(&g_M[(k1 + bi) * DDIM + c0 + bf * 4]);
        }
        #pragma unroll
        for (int r = 0; r < 8; r++) {
            float4 a0 = *reinterpret_cast<const float4*>(&SA[p][r][ty * 8]);
            float4 a1 = *reinterpret_cast<const float4*>(&SA[p][r][ty * 8 + 4]);
            float4 b  = *reinterpret_cast<const float4*>(&SB[p][r][tx * 4]);
            const float aa[8] = {a0.x, a0.y, a0.z, a0.w, a1.x, a1.y, a1.z, a1.w};
            const float bb[4] = {b.x, b.y, b.z, b.w};
            #pragma unroll
            for (int i = 0; i < 8; i++)
                #pragma unroll
                for (int j = 0; j < 4; j++) T[i][j] += aa[i] * bb[j];
        }
        if (s < 31) {
            SA[p ^ 1][ah * 4 + 0][ar] = va.x;
            SA[p ^ 1][ah * 4 + 1][ar] = va.y;
            SA[p ^ 1][ah * 4 + 2][ar] = va.z;
            SA[p ^ 1][ah * 4 + 3][ar] = va.w;
            if (tid < 128)
                *reinterpret_cast<float4*>(&SB[p ^ 1][bi][bf * 4]) = vb;
        }
        __syncthreads();
    }

    // wait for rinv release (normally already satisfied)
    if (tid == 0) {
        while (*(volatile int*)&g_c[2] < NB_RINV) __nanosleep(64);
    }
    __syncthreads();

    #pragma unroll
    for (int i = 0; i < 8; i++) {
        const int m = row0 + ty * 8 + i;
        const float rv = __ldcg(&g_rinv[m]);
        *reinterpret_cast<float4*>(&OUT[(size_t)m * DDIM + c0 + tx * 4]) =
            make_float4(T[i][0] * rv, T[i][1] * rv, T[i][2] * rv, T[i][3] * rv);
    }
}

extern "C" void kernel_launch(void* const* d_in, const int* in_sizes, int n_in,
                              void* d_out, int out_size) {
    (void)in_sizes; (void)n_in; (void)out_size;
    const float* X = (const float*)d_in[0];
    float* OUT     = (float*)d_out;

    void* cp = 0;
    cudaGetSymbolAddress(&cp, g_c);
    cudaMemsetAsync(cp, 0, 3 * sizeof(int));

    k_norm_gram<<<NB_NORM + NB_GRAM, 256>>>(X);
    k_red_out<<<NB_RED + NB_RINV + NB_OUT, 256>>>(X, OUT);
}